// round 14
// baseline (speedup 1.0000x reference)
#include <cuda_runtime.h>
#include <cuda_fp16.h>
#include <cstdint>

#define B_ 8192
#define D_ 4096
#define H_ 2048
#define K_ 512
#define LN_EPS 1e-5f

// ---------------------------------------------------------------------------
// Scratch (device globals; runtime allocation forbidden)
// ---------------------------------------------------------------------------
__device__ __align__(256) __half g_xh [(size_t)B_ * D_];   // (x - mean) fp16
__device__ __align__(256) __half g_hh [(size_t)B_ * H_];   // h fp16 (LN in-place)
__device__ __align__(256) __half g_qh [(size_t)B_ * K_];   // q_logits fp16
__device__ __align__(256) __half g_w1 [(size_t)H_ * D_];
__device__ __align__(256) __half g_w2 [(size_t)K_ * H_];
__device__ __align__(256) __half g_bt [(size_t)D_ * K_];

// ---------------------------------------------------------------------------
// Low-level helpers
// ---------------------------------------------------------------------------
__device__ __forceinline__ uint32_t smem_u32(const void* p) {
    uint32_t a;
    asm("{ .reg .u64 t; cvta.to.shared.u64 t, %1; cvt.u32.u64 %0, t; }"
        : "=r"(a) : "l"(p));
    return a;
}

__device__ __forceinline__ void cpa16(uint32_t dst, const void* src) {
    asm volatile("cp.async.cg.shared.global [%0], [%1], 16;"
                 :: "r"(dst), "l"(src) : "memory");
}
#define CP_COMMIT() asm volatile("cp.async.commit_group;" ::: "memory")
#define CP_WAIT1()  asm volatile("cp.async.wait_group 1;" ::: "memory")
#define CP_WAIT0()  asm volatile("cp.async.wait_group 0;" ::: "memory")

#define LDM_X4(r0, r1, r2, r3, addr)                                          \
    asm volatile("ldmatrix.sync.aligned.m8n8.x4.shared.b16 {%0,%1,%2,%3}, [%4];" \
                 : "=r"(r0), "=r"(r1), "=r"(r2), "=r"(r3) : "r"(addr))

__device__ __forceinline__ void mma_f16(float* c, const uint32_t* a,
                                        uint32_t b0, uint32_t b1) {
    asm volatile(
        "mma.sync.aligned.m16n8k16.row.col.f32.f16.f16.f32 "
        "{%0,%1,%2,%3}, {%4,%5,%6,%7}, {%8,%9}, {%0,%1,%2,%3};"
        : "+f"(c[0]), "+f"(c[1]), "+f"(c[2]), "+f"(c[3])
        : "r"(a[0]), "r"(a[1]), "r"(a[2]), "r"(a[3]), "r"(b0), "r"(b1));
}

// fast sigmoid: 0.5 * tanh(x/2) + 0.5   (single MUFU op vs EX2+RCP)
__device__ __forceinline__ float fast_sigmoid(float x) {
    float t;
    asm("tanh.approx.f32 %0, %1;" : "=f"(t) : "f"(x * 0.5f));
    return fmaf(0.5f, t, 0.5f);
}

// ---------------------------------------------------------------------------
// SMEM per stage (templated on M-tile MT in {128, 64}):
// K-chunk 64 fp16 (128B/row), rows padded to 144B (bank stride 36 mod 32 = 4
// -> conflict-free ldmatrix).
//   A[MT][72]  @ 0
//   B[128][72] @ MT*144
// Stage (MT+128)*144 B, 3 stages. MT=128 -> 110592 B; MT=64 -> 82944 B.
// Both run 2 CTAs/SM.
// ---------------------------------------------------------------------------
#define ROWB   144

template<int MT> struct GCfg {
    static constexpr int NT   = (MT == 128) ? 256 : 128;   // threads
    static constexpr int BOFF = MT * ROWB;
    static constexpr int STG_ = (MT + 128) * ROWB;
    static constexpr int SMEM = 3 * STG_;
};

template<int MT>
__device__ __forceinline__ void load_stage(uint32_t stb,
    const __half* __restrict__ A, const __half* __restrict__ Bw,
    int m0, int n0, int k0, int K, int tid)
{
    constexpr int NT = GCfg<MT>::NT;
    // A tile: MT rows x 8 chunks(16B)
#pragma unroll
    for (int i = 0; i < MT * 8 / NT; ++i) {
        const int idx = tid + i * NT;
        const int r = idx >> 3, c = idx & 7;
        cpa16(stb + (uint32_t)(r * ROWB + c * 16),
              A + (size_t)(m0 + r) * K + k0 + c * 8);
    }
    // B tile: 128 rows x 8 chunks
#pragma unroll
    for (int i = 0; i < 1024 / NT; ++i) {
        const int idx = tid + i * NT;
        const int r = idx >> 3, c = idx & 7;
        cpa16(stb + GCfg<MT>::BOFF + (uint32_t)(r * ROWB + c * 16),
              Bw + (size_t)(n0 + r) * K + k0 + c * 8);
    }
}

// ---------------------------------------------------------------------------
// Pure fp16 tensor-core GEMM.
// MT=128: 8 warps (wm 0..3, wn 0..1);  MT=64: 4 warps (wm 0..1, wn 0..1).
// Warp tile 32x64, m16n8k16, fp32 accum, 3-stage single-barrier pipeline.
//   EPI 0: +bias -> fp16 Oh                      (GEMM1 -> h)
//   EPI 1: +bias -> C0,C1,C2 fp32 + fp16 Oh      (GEMM2 -> q)
//   EPI 2: sigmoid -> C0 fp32                    (GEMM3 -> x_recon)
// ---------------------------------------------------------------------------
template<int EPI, int MT>
__global__ void __launch_bounds__(GCfg<MT>::NT, 2)
gemm_mma(const __half* __restrict__ A, const __half* __restrict__ Bw,
         const float* __restrict__ bias,
         float* __restrict__ C0, float* __restrict__ C1, float* __restrict__ C2,
         __half* __restrict__ Oh,
         int N, int K)
{
    constexpr int STGB = GCfg<MT>::STG_;
    extern __shared__ char smem[];
    const uint32_t sb = smem_u32(smem);

    const int tid  = threadIdx.x;
    const int lane = tid & 31;
    const int wid  = tid >> 5;
    const int wm   = (MT == 128) ? (wid & 3) : (wid & 1);
    const int wn   = (MT == 128) ? (wid >> 2) : (wid >> 1);
    const int m0 = blockIdx.y * MT;
    const int n0 = blockIdx.x * 128;
    const int NC = K >> 6;

    const int lrow  = lane & 15;
    const int lcolb = ((lane >> 4) << 4);   // 0 or 16 bytes

    float acc[2][8][4];
#pragma unroll
    for (int m = 0; m < 2; ++m)
#pragma unroll
        for (int n = 0; n < 8; ++n)
#pragma unroll
            for (int j = 0; j < 4; ++j) acc[m][n][j] = 0.f;

    // prologue: chunks 0,1 -> stages 0,1
    load_stage<MT>(sb,        A, Bw, m0, n0, 0,  K, tid); CP_COMMIT();
    load_stage<MT>(sb + STGB, A, Bw, m0, n0, 64, K, tid); CP_COMMIT();

    uint32_t cur = 0;      // stage of chunk c
    for (int c = 0; c < NC; ++c) {
        if (c + 1 < NC) CP_WAIT1(); else CP_WAIT0();
        __syncthreads();   // single barrier: visibility + WAR protection

        // prefetch chunk c+2 into stage (cur+2)%3
        if (c + 2 < NC) {
            uint32_t ls = cur + 2; if (ls >= 3) ls -= 3;
            load_stage<MT>(sb + ls * STGB, A, Bw, m0, n0, (c + 2) << 6, K, tid);
            CP_COMMIT();
        }

        const uint32_t stb = sb + cur * STGB;
        const uint32_t abase = stb + (wm * 32 + lrow) * ROWB + lcolb;
        const uint32_t bbase = stb + GCfg<MT>::BOFF + (wn * 64 + lrow) * ROWB + lcolb;

#pragma unroll
        for (int kk = 0; kk < 4; ++kk) {
            const uint32_t ko = kk * 32;   // 16 elems = 32 bytes
            uint32_t a[2][4], b[4][4];
#pragma unroll
            for (int m = 0; m < 2; ++m) {
                const uint32_t ao = abase + m * 16 * ROWB + ko;
                LDM_X4(a[m][0], a[m][1], a[m][2], a[m][3], ao);
            }
#pragma unroll
            for (int nt = 0; nt < 4; ++nt) {
                const uint32_t bo = bbase + nt * 16 * ROWB + ko;
                LDM_X4(b[nt][0], b[nt][1], b[nt][2], b[nt][3], bo);
            }
#pragma unroll
            for (int m = 0; m < 2; ++m)
#pragma unroll
                for (int nt = 0; nt < 4; ++nt) {
                    mma_f16(acc[m][2 * nt],     a[m], b[nt][0], b[nt][2]);
                    mma_f16(acc[m][2 * nt + 1], a[m], b[nt][1], b[nt][3]);
                }
        }
        ++cur; if (cur == 3) cur = 0;
    }

    // ------------------------------ epilogue ------------------------------
    const int rbase = m0 + wm * 32 + (lane >> 2);
    const int cbase = n0 + wn * 64 + 2 * (lane & 3);
#pragma unroll
    for (int m = 0; m < 2; ++m) {
        const int row = rbase + m * 16;
#pragma unroll
        for (int n = 0; n < 8; ++n) {
            const int col = cbase + n * 8;
            float v[4] = {acc[m][n][0], acc[m][n][1], acc[m][n][2], acc[m][n][3]};
            if (EPI == 0 || EPI == 1) {
                const float bb0 = bias[col], bb1 = bias[col + 1];
                v[0] += bb0; v[1] += bb1; v[2] += bb0; v[3] += bb1;
            }
            if (EPI == 2) {
#pragma unroll
                for (int j = 0; j < 4; ++j) v[j] = fast_sigmoid(v[j]);
            }
            const size_t o0 = (size_t)row * N + col;
            const size_t o1 = (size_t)(row + 8) * N + col;
            if (EPI == 0) {
                *reinterpret_cast<__half2*>(Oh + o0) = __floats2half2_rn(v[0], v[1]);
                *reinterpret_cast<__half2*>(Oh + o1) = __floats2half2_rn(v[2], v[3]);
            } else {
                *reinterpret_cast<float2*>(C0 + o0) = make_float2(v[0], v[1]);
                *reinterpret_cast<float2*>(C0 + o1) = make_float2(v[2], v[3]);
                if (EPI == 1) {
                    *reinterpret_cast<float2*>(C1 + o0) = make_float2(v[0], v[1]);
                    *reinterpret_cast<float2*>(C1 + o1) = make_float2(v[2], v[3]);
                    *reinterpret_cast<float2*>(C2 + o0) = make_float2(v[0], v[1]);
                    *reinterpret_cast<float2*>(C2 + o1) = make_float2(v[2], v[3]);
                    *reinterpret_cast<__half2*>(Oh + o0) = __floats2half2_rn(v[0], v[1]);
                    *reinterpret_cast<__half2*>(Oh + o1) = __floats2half2_rn(v[2], v[3]);
                }
            }
        }
    }
}

// ---------------------------------------------------------------------------
// Fused fp32 -> fp16 conversion of all four inputs in ONE launch, MLP=4.
// Each block covers 1024 quads (256 threads x 4 quads, stride 256).
// ---------------------------------------------------------------------------
#define XQ    (B_ * D_ / 4)
#define W1Q   (H_ * D_ / 4)
#define W2Q   (K_ * H_ / 4)
#define BTQ   (D_ * K_ / 4)
#define XBLK  (XQ  / 1024)
#define W1BLK (W1Q / 1024)
#define W2BLK (W2Q / 1024)
#define BTBLK (BTQ / 1024)

__global__ void __launch_bounds__(256)
cvt_all(const float* __restrict__ x,    const float* __restrict__ mean,
        __half* __restrict__ xh,
        const float* __restrict__ W1,   __half* __restrict__ w1,
        const float* __restrict__ W2,   __half* __restrict__ w2,
        const float* __restrict__ bt_in,__half* __restrict__ bt)
{
    const int bid = blockIdx.x;
    const int tid = threadIdx.x;
    const float* src; __half* dst; int qb; bool with_mean = false;

    if (bid < XBLK) {
        src = x; dst = xh; qb = bid * 1024 + tid; with_mean = true;
    } else if (bid < XBLK + W1BLK) {
        src = W1; dst = w1; qb = (bid - XBLK) * 1024 + tid;
    } else if (bid < XBLK + W1BLK + W2BLK) {
        src = W2; dst = w2; qb = (bid - XBLK - W1BLK) * 1024 + tid;
    } else {
        src = bt_in; dst = bt; qb = (bid - XBLK - W1BLK - W2BLK) * 1024 + tid;
    }

    float4 v[4];
#pragma unroll
    for (int k = 0; k < 4; ++k)
        v[k] = reinterpret_cast<const float4*>(src)[qb + k * 256];

    if (with_mean) {
        const int dmask = D_ - 1;
#pragma unroll
        for (int k = 0; k < 4; ++k) {
            const int e = (qb + k * 256) * 4;
            v[k].x -= mean[(e + 0) & dmask]; v[k].y -= mean[(e + 1) & dmask];
            v[k].z -= mean[(e + 2) & dmask]; v[k].w -= mean[(e + 3) & dmask];
        }
    }

#pragma unroll
    for (int k = 0; k < 4; ++k) {
        const int e = (qb + k * 256) * 4;
        *reinterpret_cast<__half2*>(dst + e)     = __floats2half2_rn(v[k].x, v[k].y);
        *reinterpret_cast<__half2*>(dst + e + 2) = __floats2half2_rn(v[k].z, v[k].w);
    }
}

// ---------------------------------------------------------------------------
// LayerNorm + ReLU over H, IN-PLACE on fp16 h. One block per row,
// 256 threads x 8 halfs (one uint4) each.
// ---------------------------------------------------------------------------
__global__ void __launch_bounds__(256)
ln_relu(__half* __restrict__ h, const float* __restrict__ w,
        const float* __restrict__ b)
{
    const int row = blockIdx.x;
    const int tid = threadIdx.x;
    uint4* hr = reinterpret_cast<uint4*>(h + (size_t)row * H_);

    uint4 raw = hr[tid];
    const __half2* hp = reinterpret_cast<const __half2*>(&raw);
    float f[8];
#pragma unroll
    for (int j = 0; j < 4; ++j) {
        float2 p = __half22float2(hp[j]);
        f[2 * j] = p.x; f[2 * j + 1] = p.y;
    }

    float s = 0.f, sq = 0.f;
#pragma unroll
    for (int j = 0; j < 8; ++j) { s += f[j]; sq += f[j] * f[j]; }
#pragma unroll
    for (int o = 16; o; o >>= 1) {
        s  += __shfl_xor_sync(0xffffffffu, s,  o);
        sq += __shfl_xor_sync(0xffffffffu, sq, o);
    }
    __shared__ float red[16];
    const int wd = tid >> 5, lane = tid & 31;
    if (lane == 0) { red[wd] = s; red[8 + wd] = sq; }
    __syncthreads();
    float ts = 0.f, tq = 0.f;
#pragma unroll
    for (int i = 0; i < 8; ++i) { ts += red[i]; tq += red[8 + i]; }

    const float mu  = ts * (1.f / H_);
    const float var = tq * (1.f / H_) - mu * mu;
    const float rr  = rsqrtf(var + LN_EPS);

    const float4 w0 = reinterpret_cast<const float4*>(w)[tid * 2];
    const float4 w1 = reinterpret_cast<const float4*>(w)[tid * 2 + 1];
    const float4 b0 = reinterpret_cast<const float4*>(b)[tid * 2];
    const float4 b1 = reinterpret_cast<const float4*>(b)[tid * 2 + 1];

    float o[8];
    o[0] = fmaxf((f[0] - mu) * rr * w0.x + b0.x, 0.f);
    o[1] = fmaxf((f[1] - mu) * rr * w0.y + b0.y, 0.f);
    o[2] = fmaxf((f[2] - mu) * rr * w0.z + b0.z, 0.f);
    o[3] = fmaxf((f[3] - mu) * rr * w0.w + b0.w, 0.f);
    o[4] = fmaxf((f[4] - mu) * rr * w1.x + b1.x, 0.f);
    o[5] = fmaxf((f[5] - mu) * rr * w1.y + b1.y, 0.f);
    o[6] = fmaxf((f[6] - mu) * rr * w1.z + b1.z, 0.f);
    o[7] = fmaxf((f[7] - mu) * rr * w1.w + b1.w, 0.f);

    uint4 outw;
    __half2* op = reinterpret_cast<__half2*>(&outw);
    op[0] = __floats2half2_rn(o[0], o[1]);
    op[1] = __floats2half2_rn(o[2], o[3]);
    op[2] = __floats2half2_rn(o[4], o[5]);
    op[3] = __floats2half2_rn(o[6], o[7]);
    hr[tid] = outw;
}

// ---------------------------------------------------------------------------
// kernel_launch
// ---------------------------------------------------------------------------
extern "C" void kernel_launch(void* const* d_in, const int* in_sizes, int n_in,
                              void* d_out, int out_size)
{
    const float* x    = (const float*)d_in[0];
    const float* beta = (const float*)d_in[1];
    const float* mean = (const float*)d_in[2];
    const float* W1   = (const float*)d_in[3];
    const float* b1   = (const float*)d_in[4];
    const float* lnw  = (const float*)d_in[5];
    const float* lnb  = (const float*)d_in[6];
    const float* W2   = (const float*)d_in[7];
    const float* b2   = (const float*)d_in[8];

    float* out = (float*)d_out;
    float* q0 = out;                        // [B, K]
    float* xr = out + (size_t)B_ * K_;      // [B, D]
    float* q1 = xr + (size_t)B_ * D_;       // [B, K]
    float* q2 = q1 + (size_t)B_ * K_;       // [B, K]

    void *p_xh, *p_hh, *p_qh, *p_w1, *p_w2, *p_bt;
    cudaGetSymbolAddress(&p_xh, g_xh);
    cudaGetSymbolAddress(&p_hh, g_hh);
    cudaGetSymbolAddress(&p_qh, g_qh);
    cudaGetSymbolAddress(&p_w1, g_w1);
    cudaGetSymbolAddress(&p_w2, g_w2);
    cudaGetSymbolAddress(&p_bt, g_bt);

    __half *xh = (__half*)p_xh, *hh = (__half*)p_hh, *qh = (__half*)p_qh;
    __half *w1 = (__half*)p_w1, *w2 = (__half*)p_w2, *bt = (__half*)p_bt;

    cudaFuncSetAttribute(gemm_mma<0, 128>, cudaFuncAttributeMaxDynamicSharedMemorySize, GCfg<128>::SMEM);
    cudaFuncSetAttribute(gemm_mma<1, 64>,  cudaFuncAttributeMaxDynamicSharedMemorySize, GCfg<64>::SMEM);
    cudaFuncSetAttribute(gemm_mma<2, 128>, cudaFuncAttributeMaxDynamicSharedMemorySize, GCfg<128>::SMEM);

    // #1: all fp32->fp16 conversions in one launch (MLP=4)
    cvt_all<<<XBLK + W1BLK + W2BLK + BTBLK, 256>>>(x, mean, xh, W1, w1, W2, w2, beta, bt);

    // #2: GEMM1: h = (x-mean) @ W1^T + b1 -> fp16 hh   [8192, 2048], K=4096
    gemm_mma<0, 128><<<dim3(H_ / 128, B_ / 128), GCfg<128>::NT, GCfg<128>::SMEM>>>(
        xh, w1, b1, nullptr, nullptr, nullptr, hh, H_, D_);

    // #3: LayerNorm + ReLU in place on fp16 hh
    ln_relu<<<B_, 256>>>(hh, lnw, lnb);

    // #4: GEMM2: q = h @ W2^T + b2   [8192, 512], K=2048 -> q0/q1/q2 + fp16 q
    //     64-row tile -> 512 CTAs (1.73 waves) to avoid sub-wave starvation.
    gemm_mma<1, 64><<<dim3(K_ / 128, B_ / 64), GCfg<64>::NT, GCfg<64>::SMEM>>>(
        hh, w2, b2, q0, q1, q2, qh, K_, H_);

    // #5: GEMM3: x_recon = sigmoid(q @ beta^T)   [8192, 4096], K=512
    gemm_mma<2, 128><<<dim3(D_ / 128, B_ / 128), GCfg<128>::NT, GCfg<128>::SMEM>>>(
        qh, bt, nullptr, xr, nullptr, nullptr, nullptr, D_, K_);
}